// round 9
// baseline (speedup 1.0000x reference)
#include <cuda_runtime.h>

// Round 9: attention QK^T on tensor cores (3xTF32 mma, m16n8k8) with Q/K
// hi/lo splits precomputed in the qkv epilogue (no in-loop cvt). Softmax and
// f32x2 PV unchanged. Projections = R8 (measured).

#define EMBED 1024
#define NHEAD 16
#define HDIM  64
#define BATCH 2
#define SEQ   2048
#define MTOT  (BATCH*SEQ)

#define PBM 128
#define PBN 128
#define PBK 16
#define PADT 136

#define PADP 68
#define ATTN_FLOATS (6*64*PADP + 128)  // Qhi,Qlo,Khi,Klo,Vs,Ps + corr/l
#define ATTN_SMEM   (ATTN_FLOATS*4)

typedef unsigned long long u64;
typedef unsigned int u32;

// ---- f32x2 helpers ----
__device__ __forceinline__ u64 pk2(float a) {
    u64 r; asm("mov.b64 %0, {%1, %1};" : "=l"(r) : "f"(a)); return r;
}
__device__ __forceinline__ void fma2(u64& d, u64 a, u64 b) {
    asm("fma.rn.f32x2 %0, %1, %2, %0;" : "+l"(d) : "l"(a), "l"(b));
}
__device__ __forceinline__ void mul2(u64& d, u64 a) {
    asm("mul.rn.f32x2 %0, %0, %1;" : "+l"(d) : "l"(a));
}
__device__ __forceinline__ float2 up2(u64 v) {
    float2 r; asm("mov.b64 {%0, %1}, %2;" : "=f"(r.x), "=f"(r.y) : "l"(v)); return r;
}

// ---- tf32 mma helpers ----
__device__ __forceinline__ void split_tf32(float a, u32& hi, u32& lo) {
    asm("cvt.rna.tf32.f32 %0, %1;" : "=r"(hi) : "f"(a));
    float r = a - __uint_as_float(hi);
    asm("cvt.rna.tf32.f32 %0, %1;" : "=r"(lo) : "f"(r));
}
__device__ __forceinline__ void mma8(float* c, const u32* a, const u32* b) {
    asm("mma.sync.aligned.m16n8k8.row.col.f32.tf32.tf32.f32 "
        "{%0,%1,%2,%3}, {%4,%5,%6,%7}, {%8,%9}, {%0,%1,%2,%3};"
        : "+f"(c[0]), "+f"(c[1]), "+f"(c[2]), "+f"(c[3])
        : "r"(a[0]), "r"(a[1]), "r"(a[2]), "r"(a[3]), "r"(b[0]), "r"(b[1]));
}

// Scratch
__device__ u32   g_qhi[BATCH*NHEAD*SEQ*HDIM];
__device__ u32   g_qlo[BATCH*NHEAD*SEQ*HDIM];
__device__ u32   g_khi[BATCH*NHEAD*SEQ*HDIM];
__device__ u32   g_klo[BATCH*NHEAD*SEQ*HDIM];
__device__ float g_v  [BATCH*NHEAD*SEQ*HDIM];
__device__ float g_h  [MTOT*EMBED];

// ---------------------------------------------------------------------------
// 128x128 tf32-mma GEMM body (R8, measured): in-loop splits.
// ---------------------------------------------------------------------------
#define PROJ_MMA_BODY(APTR, WPTR)                                              \
    __shared__ float As[PBK][PADT];                                            \
    __shared__ float Bs[PBK][PADT];                                            \
    const int tid  = threadIdx.x;                                              \
    const int lane = tid & 31;                                                 \
    const int wid  = tid >> 5;                                                 \
    const int m0 = blockIdx.y * PBM;                                           \
    const int n0 = blockIdx.x * PBN;                                           \
    const int wm = (wid >> 2) << 6;                                            \
    const int wn = (wid & 3) << 5;                                             \
    const int g4 = lane >> 2;                                                  \
    const int t4 = lane & 3;                                                   \
    const int lr  = tid >> 1;                                                  \
    const int lc8 = (tid & 1) << 3;                                            \
    const float* Ap = (APTR) + (size_t)(m0 + lr) * EMBED + lc8;                \
    const float* Wp = (WPTR) + (size_t)(n0 + lr) * EMBED + lc8;                \
    float c[4][4][4];                                                          \
    _Pragma("unroll")                                                          \
    for (int mi = 0; mi < 4; mi++)                                             \
        _Pragma("unroll")                                                      \
        for (int ni = 0; ni < 4; ni++)                                         \
            _Pragma("unroll")                                                  \
            for (int u = 0; u < 4; u++) c[mi][ni][u] = 0.f;                    \
    float4 a0 = *(const float4*)(Ap);                                          \
    float4 a1 = *(const float4*)(Ap + 4);                                      \
    float4 w0 = *(const float4*)(Wp);                                          \
    float4 w1 = *(const float4*)(Wp + 4);                                      \
    for (int kb = 0; kb < EMBED; kb += PBK) {                                  \
        __syncthreads();                                                       \
        As[lc8+0][lr] = a0.x; As[lc8+1][lr] = a0.y;                            \
        As[lc8+2][lr] = a0.z; As[lc8+3][lr] = a0.w;                            \
        As[lc8+4][lr] = a1.x; As[lc8+5][lr] = a1.y;                            \
        As[lc8+6][lr] = a1.z; As[lc8+7][lr] = a1.w;                            \
        Bs[lc8+0][lr] = w0.x; Bs[lc8+1][lr] = w0.y;                            \
        Bs[lc8+2][lr] = w0.z; Bs[lc8+3][lr] = w0.w;                            \
        Bs[lc8+4][lr] = w1.x; Bs[lc8+5][lr] = w1.y;                            \
        Bs[lc8+6][lr] = w1.z; Bs[lc8+7][lr] = w1.w;                            \
        __syncthreads();                                                       \
        if (kb + PBK < EMBED) {                                                \
            a0 = *(const float4*)(Ap + kb + PBK);                              \
            a1 = *(const float4*)(Ap + kb + PBK + 4);                          \
            w0 = *(const float4*)(Wp + kb + PBK);                              \
            w1 = *(const float4*)(Wp + kb + PBK + 4);                          \
        }                                                                      \
        _Pragma("unroll")                                                      \
        for (int k8 = 0; k8 < PBK; k8 += 8) {                                  \
            u32 bhi[4][2], blo[4][2];                                          \
            _Pragma("unroll")                                                  \
            for (int ni = 0; ni < 4; ni++) {                                   \
                float f0 = Bs[k8 + t4    ][wn + ni*8 + g4];                    \
                float f1 = Bs[k8 + t4 + 4][wn + ni*8 + g4];                    \
                split_tf32(f0, bhi[ni][0], blo[ni][0]);                        \
                split_tf32(f1, bhi[ni][1], blo[ni][1]);                        \
            }                                                                  \
            _Pragma("unroll")                                                  \
            for (int mi = 0; mi < 4; mi++) {                                   \
                const int r = wm + mi*16 + g4;                                 \
                float f0 = As[k8 + t4    ][r];                                 \
                float f1 = As[k8 + t4    ][r + 8];                             \
                float f2 = As[k8 + t4 + 4][r];                                 \
                float f3 = As[k8 + t4 + 4][r + 8];                             \
                u32 ahi[4], alo[4];                                            \
                split_tf32(f0, ahi[0], alo[0]);                                \
                split_tf32(f1, ahi[1], alo[1]);                                \
                split_tf32(f2, ahi[2], alo[2]);                                \
                split_tf32(f3, ahi[3], alo[3]);                                \
                _Pragma("unroll")                                              \
                for (int ni = 0; ni < 4; ni++) {                               \
                    mma8(c[mi][ni], ahi, bhi[ni]);                             \
                    mma8(c[mi][ni], ahi, blo[ni]);                             \
                    mma8(c[mi][ni], alo, bhi[ni]);                             \
                }                                                              \
            }                                                                  \
        }                                                                      \
    }

// ---------------------------------------------------------------------------
// QKV projection. z=0 -> Q splits, z=1 -> K splits, z=2 -> V fp32.
// ---------------------------------------------------------------------------
__global__ __launch_bounds__(256, 2) void qkv_proj_kernel(
    const float* __restrict__ X,
    const float* __restrict__ Wq, const float* __restrict__ bq,
    const float* __restrict__ Wk, const float* __restrict__ bk,
    const float* __restrict__ Wv, const float* __restrict__ bv)
{
    const int z = blockIdx.z;
    const float *W, *bias;
    if (z == 0)      { W = Wq; bias = bq; }
    else if (z == 1) { W = Wk; bias = bk; }
    else             { W = Wv; bias = bv; }
    u32* Ohi = (z == 0) ? g_qhi : g_khi;
    u32* Olo = (z == 0) ? g_qlo : g_klo;

    PROJ_MMA_BODY(X, W)

#pragma unroll
    for (int mi = 0; mi < 4; mi++) {
#pragma unroll
        for (int ni = 0; ni < 4; ni++) {
            const int col = n0 + wn + ni*8 + 2*t4;
            const int h   = col >> 6;
            const int d   = col & 63;
            float2 bb = *(const float2*)&bias[col];
#pragma unroll
            for (int half = 0; half < 2; half++) {
                int row = m0 + wm + mi*16 + g4 + half*8;
                int b   = row >> 11;
                int n   = row & (SEQ - 1);
                float ox = c[mi][ni][2*half+0] + bb.x;
                float oy = c[mi][ni][2*half+1] + bb.y;
                size_t off = ((size_t)(b*NHEAD + h)*SEQ + n)*HDIM + d;
                if (z == 2) {
                    *(float2*)&g_v[off] = make_float2(ox, oy);
                } else {
                    u32 hx, lx, hy, ly;
                    split_tf32(ox, hx, lx);
                    split_tf32(oy, hy, ly);
                    uint2 hv; hv.x = hx; hv.y = hy;
                    uint2 lv; lv.x = lx; lv.y = ly;
                    *(uint2*)&Ohi[off] = hv;
                    *(uint2*)&Olo[off] = lv;
                }
            }
        }
    }
}

// ---------------------------------------------------------------------------
__global__ __launch_bounds__(256, 2) void out_proj_kernel(
    const float* __restrict__ Wo, const float* __restrict__ bo,
    float* __restrict__ Outp)
{
    PROJ_MMA_BODY(g_h, Wo)

#pragma unroll
    for (int mi = 0; mi < 4; mi++) {
#pragma unroll
        for (int ni = 0; ni < 4; ni++) {
            const int col = n0 + wn + ni*8 + 2*t4;
            float2 bb = *(const float2*)&bo[col];
#pragma unroll
            for (int half = 0; half < 2; half++) {
                int row = m0 + wm + mi*16 + g4 + half*8;
                float2 o = make_float2(c[mi][ni][2*half+0] + bb.x,
                                       c[mi][ni][2*half+1] + bb.y);
                *(float2*)&Outp[(size_t)row * EMBED + col] = o;
            }
        }
    }
}

// ---------------------------------------------------------------------------
// Flash attention: QK via 3xTF32 mma (precomputed splits), SIMT softmax,
// f32x2 SIMT PV with 4-way key-split partial accumulators.
// ---------------------------------------------------------------------------
__global__ __launch_bounds__(256, 2) void attn_kernel()
{
    extern __shared__ float sm[];
    u32*   Qhi = (u32*)sm;
    u32*   Qlo = (u32*)(sm + 64*PADP);
    u32*   Khi = (u32*)(sm + 2*64*PADP);
    u32*   Klo = (u32*)(sm + 3*64*PADP);
    float* Vs  = sm + 4*64*PADP;
    float* Ps  = sm + 5*64*PADP;
    float* corr_s = sm + 6*64*PADP;
    float* l_s    = corr_s + 64;

    const int tid  = threadIdx.x;
    const int lane = tid & 31;
    const int wid  = tid >> 5;
    const int bh  = blockIdx.y;
    const int q0  = blockIdx.x << 6;
    const size_t base = (size_t)bh * SEQ * HDIM;

    const int lr = tid >> 2;           // 0..63 staging row
    const int dq = (tid & 3) << 4;     // staging d-offset (16 elems)
    const int ty = tid >> 4;           // softmax mapping
    const int tx = tid & 15;
    const int g   = tid >> 6;          // PV key-split group
    const int t64 = tid & 63;
    const int tr  = t64 >> 3;
    const int tc  = t64 & 7;
    // QK mma mapping: 8 warps = 4(m) x 2(n)
    const int qm0 = (wid >> 1) << 4;   // warp q-row base (16 rows)
    const int wn  = (wid & 1) << 5;    // warp k-col half (32 cols)
    const int g4  = lane >> 2;
    const int t4  = lane & 3;

    // Stage Q splits once: [q][d]
#pragma unroll
    for (int it = 0; it < 4; it++) {
        *(uint4*)&Qhi[lr*PADP + dq + it*4] =
            *(const uint4*)&g_qhi[base + (size_t)(q0 + lr)*HDIM + dq + it*4];
        *(uint4*)&Qlo[lr*PADP + dq + it*4] =
            *(const uint4*)&g_qlo[base + (size_t)(q0 + lr)*HDIM + dq + it*4];
    }

    float m_run[4], l_run[4];
    u64 o2[8][4];
#pragma unroll
    for (int i = 0; i < 4; i++) { m_run[i] = -1e30f; l_run[i] = 0.f; }
#pragma unroll
    for (int i = 0; i < 8; i++)
#pragma unroll
        for (int j = 0; j < 4; j++) o2[i][j] = 0ull;

    for (int k0 = 0; k0 < SEQ; k0 += 64) {
        __syncthreads();   // prev PV done; Q staged (iter 0)
        // Stage K splits [k][d] + V [k][d]
#pragma unroll
        for (int it = 0; it < 4; it++) {
            *(uint4*)&Khi[lr*PADP + dq + it*4] =
                *(const uint4*)&g_khi[base + (size_t)(k0 + lr)*HDIM + dq + it*4];
            *(uint4*)&Klo[lr*PADP + dq + it*4] =
                *(const uint4*)&g_klo[base + (size_t)(k0 + lr)*HDIM + dq + it*4];
            *(float4*)&Vs[lr*PADP + dq + it*4] =
                *(const float4*)&g_v[base + (size_t)(k0 + lr)*HDIM + dq + it*4];
        }
        __syncthreads();

        // ---- S = Q K^T via 3xTF32 mma ----
        float c[4][4];
#pragma unroll
        for (int ni = 0; ni < 4; ni++)
#pragma unroll
            for (int u = 0; u < 4; u++) c[ni][u] = 0.f;

#pragma unroll
        for (int k8 = 0; k8 < 64; k8 += 8) {
            u32 ahi[4], alo[4];
            ahi[0] = Qhi[(qm0+g4  )*PADP + k8 + t4    ];
            ahi[1] = Qhi[(qm0+g4+8)*PADP + k8 + t4    ];
            ahi[2] = Qhi[(qm0+g4  )*PADP + k8 + t4 + 4];
            ahi[3] = Qhi[(qm0+g4+8)*PADP + k8 + t4 + 4];
            alo[0] = Qlo[(qm0+g4  )*PADP + k8 + t4    ];
            alo[1] = Qlo[(qm0+g4+8)*PADP + k8 + t4    ];
            alo[2] = Qlo[(qm0+g4  )*PADP + k8 + t4 + 4];
            alo[3] = Qlo[(qm0+g4+8)*PADP + k8 + t4 + 4];
#pragma unroll
            for (int ni = 0; ni < 4; ni++) {
                const int kr = wn + ni*8 + g4;
                u32 bhi[2], blo[2];
                bhi[0] = Khi[kr*PADP + k8 + t4];
                bhi[1] = Khi[kr*PADP + k8 + t4 + 4];
                blo[0] = Klo[kr*PADP + k8 + t4];
                blo[1] = Klo[kr*PADP + k8 + t4 + 4];
                mma8(c[ni], ahi, bhi);
                mma8(c[ni], ahi, blo);
                mma8(c[ni], alo, bhi);
            }
        }

        // write raw S fragments to Ps
#pragma unroll
        for (int ni = 0; ni < 4; ni++) {
            const int col = wn + ni*8 + 2*t4;
            *(float2*)&Ps[(qm0+g4  )*PADP + col] = make_float2(c[ni][0], c[ni][1]);
            *(float2*)&Ps[(qm0+g4+8)*PADP + col] = make_float2(c[ni][2], c[ni][3]);
        }
        __syncthreads();   // S complete

        // ---- online softmax (rows ty*4+i, cols tx*4) ----
#pragma unroll
        for (int i = 0; i < 4; i++) {
            float4 sv = *(const float4*)&Ps[((ty<<2)+i)*PADP + (tx<<2)];
            float s[4] = {sv.x*8.0f, sv.y*8.0f, sv.z*8.0f, sv.w*8.0f};
            float mx = fmaxf(fmaxf(s[0], s[1]), fmaxf(s[2], s[3]));
            mx = fmaxf(mx, __shfl_xor_sync(0xffffffffu, mx, 8, 16));
            mx = fmaxf(mx, __shfl_xor_sync(0xffffffffu, mx, 4, 16));
            mx = fmaxf(mx, __shfl_xor_sync(0xffffffffu, mx, 2, 16));
            mx = fmaxf(mx, __shfl_xor_sync(0xffffffffu, mx, 1, 16));
            float mnew = fmaxf(m_run[i], mx);
            float corr = __expf(m_run[i] - mnew);
            float rs = 0.f;
#pragma unroll
            for (int j = 0; j < 4; j++) {
                float p = __expf(s[j] - mnew);
                s[j] = p; rs += p;
            }
            rs += __shfl_xor_sync(0xffffffffu, rs, 8, 16);
            rs += __shfl_xor_sync(0xffffffffu, rs, 4, 16);
            rs += __shfl_xor_sync(0xffffffffu, rs, 2, 16);
            rs += __shfl_xor_sync(0xffffffffu, rs, 1, 16);
            l_run[i] = l_run[i] * corr + rs;
            m_run[i] = mnew;
            if (tx == 0) corr_s[(ty<<2)+i] = corr;
            *(float4*)&Ps[((ty<<2)+i)*PADP + (tx<<2)] =
                make_float4(s[0], s[1], s[2], s[3]);
        }
        __syncthreads();   // P, corr ready

        // ---- PV (f32x2 SIMT, 4-way key split) ----
#pragma unroll
        for (int rr = 0; rr < 8; rr++) {
            u64 c2 = pk2(corr_s[tr*8 + rr]);
            mul2(o2[rr][0], c2); mul2(o2[rr][1], c2);
            mul2(o2[rr][2], c2); mul2(o2[rr][3], c2);
        }

        const int kbase = g << 4;
#pragma unroll
        for (int c4 = 0; c4 < 16; c4 += 4) {
            const int kk = kbase + c4;
            u64 v2[4][4];
#pragma unroll
            for (int u = 0; u < 4; u++) {
                const u64* vp0 = (const u64*)&Vs[(kk+u)*PADP + (tc<<2)];
                const u64* vp1 = (const u64*)&Vs[(kk+u)*PADP + 32 + (tc<<2)];
                v2[u][0] = vp0[0]; v2[u][1] = vp0[1];
                v2[u][2] = vp1[0]; v2[u][3] = vp1[1];
            }
#pragma unroll
            for (int rr = 0; rr < 8; rr++) {
                float4 p = *(const float4*)&Ps[(tr*8+rr)*PADP + kk];
                float pa[4] = {p.x, p.y, p.z, p.w};
#pragma unroll
                for (int u = 0; u < 4; u++) {
                    u64 p2 = pk2(pa[u]);
                    fma2(o2[rr][0], p2, v2[u][0]);
                    fma2(o2[rr][1], p2, v2[u][1]);
                    fma2(o2[rr][2], p2, v2[u][2]);
                    fma2(o2[rr][3], p2, v2[u][3]);
                }
            }
        }
    }

    // unpack
    float o[8][8];
#pragma unroll
    for (int rr = 0; rr < 8; rr++) {
        float2 p0 = up2(o2[rr][0]), p1 = up2(o2[rr][1]);
        float2 p2 = up2(o2[rr][2]), p3 = up2(o2[rr][3]);
        o[rr][0]=p0.x; o[rr][1]=p0.y; o[rr][2]=p1.x; o[rr][3]=p1.y;
        o[rr][4]=p2.x; o[rr][5]=p2.y; o[rr][6]=p3.x; o[rr][7]=p3.y;
    }

    if (tx == 0) {
#pragma unroll
        for (int i = 0; i < 4; i++) l_s[(ty<<2)+i] = l_run[i];
    }
    __syncthreads();   // PV done; Qhi/Qlo/Khi regions reusable as merge bufs

    if (g > 0) {
        float* mb = sm + (g-1)*(64*PADP) + t64*PADP;
#pragma unroll
        for (int rr = 0; rr < 8; rr++) {
            *(float4*)&mb[rr*8 + 0] = make_float4(o[rr][0], o[rr][1], o[rr][2], o[rr][3]);
            *(float4*)&mb[rr*8 + 4] = make_float4(o[rr][4], o[rr][5], o[rr][6], o[rr][7]);
        }
    }
    __syncthreads();

    if (g == 0) {
        const int b = bh >> 4;
        const int h = bh & 15;
#pragma unroll
        for (int gg = 0; gg < 3; gg++) {
            const float* mb = sm + gg*(64*PADP) + t64*PADP;
#pragma unroll
            for (int rr = 0; rr < 8; rr++) {
                float4 p0 = *(const float4*)&mb[rr*8 + 0];
                float4 p1 = *(const float4*)&mb[rr*8 + 4];
                o[rr][0] += p0.x; o[rr][1] += p0.y; o[rr][2] += p0.z; o[rr][3] += p0.w;
                o[rr][4] += p1.x; o[rr][5] += p1.y; o[rr][6] += p1.z; o[rr][7] += p1.w;
            }
        }
#pragma unroll
        for (int rr = 0; rr < 8; rr++) {
            int row = tr*8 + rr;
            float inv = 1.0f / l_s[row];
            int q = q0 + row;
            float* dst = &g_h[((size_t)(b*SEQ + q))*EMBED + h*HDIM];
            *(float4*)&dst[(tc<<2)] =
                make_float4(o[rr][0]*inv, o[rr][1]*inv, o[rr][2]*inv, o[rr][3]*inv);
            *(float4*)&dst[32 + (tc<<2)] =
                make_float4(o[rr][4]*inv, o[rr][5]*inv, o[rr][6]*inv, o[rr][7]*inv);
        }
    }
}

// ---------------------------------------------------------------------------
extern "C" void kernel_launch(void* const* d_in, const int* in_sizes, int n_in,
                              void* d_out, int out_size)
{
    const float* x  = (const float*)d_in[0];
    const float* Wq = (const float*)d_in[1];
    const float* bq = (const float*)d_in[2];
    const float* Wk = (const float*)d_in[3];
    const float* bk = (const float*)d_in[4];
    const float* Wv = (const float*)d_in[5];
    const float* bv = (const float*)d_in[6];
    const float* Wo = (const float*)d_in[7];
    const float* bo = (const float*)d_in[8];
    float* out = (float*)d_out;

    cudaFuncSetAttribute(attn_kernel,
                         cudaFuncAttributeMaxDynamicSharedMemorySize, ATTN_SMEM);

    dim3 gproj(EMBED / PBN, MTOT / PBM, 3);
    qkv_proj_kernel<<<gproj, 256>>>(x, Wq, bq, Wk, bk, Wv, bv);

    dim3 gattn(SEQ / 64, BATCH * NHEAD);
    attn_kernel<<<gattn, 256, ATTN_SMEM>>>();

    dim3 gout(EMBED / PBN, MTOT / PBM);
    out_proj_kernel<<<gout, 256>>>(Wo, bo, out);
}